// round 3
// baseline (speedup 1.0000x reference)
#include <cuda_runtime.h>
#include <cstdint>

#define BATCH 4194304

// Precomputed log_softmax(W.T + b): [card*3 + action]
__device__ float d_logp[6];

__global__ void init_logp_kernel(const float* __restrict__ W,
                                 const float* __restrict__ bias) {
    if (threadIdx.x == 0 && blockIdx.x == 0) {
        #pragma unroll
        for (int c = 0; c < 2; c++) {
            // W is (3,2) row-major; x_a = W[a,c] + b[a]
            float x0 = W[0 * 2 + c] + bias[0];
            float x1 = W[1 * 2 + c] + bias[1];
            float x2 = W[2 * 2 + c] + bias[2];
            float m  = fmaxf(x0, fmaxf(x1, x2));
            float s0 = x0 - m, s1 = x1 - m, s2 = x2 - m;
            float l  = logf(expf(s0) + expf(s1) + expf(s2));
            d_logp[c * 3 + 0] = s0 - l;
            d_logp[c * 3 + 1] = s1 - l;
            d_logp[c * 3 + 2] = s2 - l;
        }
    }
}

// JAX partitionable-threefry 32-bit draw for global element index i (< 2^32):
//   (o0, o1) = threefry2x32(key=(0,42), x0=hi32(i)=0, x1=lo32(i)=i)
//   bits = o0 ^ o1
__device__ __forceinline__ uint32_t tf_bits(uint32_t ctr) {
    const uint32_t k0 = 0u;
    const uint32_t k1 = 42u;
    const uint32_t k2 = 0u ^ 42u ^ 0x1BD11BDAu;
    uint32_t x0 = 0u + k0;       // hi32(counter) = 0
    uint32_t x1 = ctr + k1;
#define TF_RND(r) { x0 += x1; x1 = __funnelshift_l(x1, x1, (r)); x1 ^= x0; }
    TF_RND(13) TF_RND(15) TF_RND(26) TF_RND(6)
    x0 += k1; x1 += k2 + 1u;
    TF_RND(17) TF_RND(29) TF_RND(16) TF_RND(24)
    x0 += k2; x1 += k0 + 2u;
    TF_RND(13) TF_RND(15) TF_RND(26) TF_RND(6)
    x0 += k0; x1 += k1 + 3u;
    TF_RND(17) TF_RND(29) TF_RND(16) TF_RND(24)
    x0 += k1; x1 += k2 + 4u;
    TF_RND(13) TF_RND(15) TF_RND(26) TF_RND(6)
    x0 += k2; x1 += k0 + 5u;
#undef TF_RND
    return x0 ^ x1;
}

// JAX uniform(minval=tiny, maxval=1) bit-exact construction
__device__ __forceinline__ float to_unif(uint32_t bits) {
    float f = __uint_as_float((bits >> 9) | 0x3f800000u) - 1.0f;
    return fmaxf(f, 1.17549435e-38f);
}

__global__ void __launch_bounds__(256)
sample_kernel(const int* __restrict__ cards, float* __restrict__ out) {
    int b = blockIdx.x * blockDim.x + threadIdx.x;
    if (b >= BATCH) return;

    float lp[6];
    #pragma unroll
    for (int i = 0; i < 6; i++) lp[i] = d_logp[i];

    // Element index in the (B, 2, 3) gumbel tensor: i = 6b + 3c + a
    uint32_t base = (uint32_t)b * 6u;

    int   cf[2];
    float lcf[2];
    #pragma unroll
    for (int c = 0; c < 2; c++) {
        // score_a = logp_a + gumbel_a; gumbel = -log(-log(u)). First-max tie rule
        // (matches jnp.argmax).
        float best = lp[c * 3 + 0] - logf(-logf(to_unif(tf_bits(base + c * 3 + 0))));
        int   bi   = 0;
        #pragma unroll
        for (int a = 1; a < 3; a++) {
            float s = lp[c * 3 + a] - logf(-logf(to_unif(tf_bits(base + c * 3 + a))));
            if (s > best) { best = s; bi = a; }
        }
        cf[c]  = bi;
        lcf[c] = lp[c * 3 + bi];
    }

    int card = cards[b];                 // in {0,1}
    int u0   = (card == 0) ? cf[0] : cf[1];

    float2 bel;
    if (cf[0] == cf[1])       bel = make_float2(0.5f, 0.5f);
    else if (card == 0)       bel = make_float2(1.0f, 0.0f);
    else                      bel = make_float2(0.0f, 1.0f);

    out[b] = (float)u0;
    reinterpret_cast<float2*>(out + BATCH)[b]             = bel;
    reinterpret_cast<float2*>(out + 3 * (size_t)BATCH)[b] = make_float2(lcf[0], lcf[1]);
}

extern "C" void kernel_launch(void* const* d_in, const int* in_sizes, int n_in,
                              void* d_out, int out_size) {
    const int*   cards = (const int*)d_in[0];     // cards_0: (B,) int32
    const float* W     = (const float*)d_in[1];   // (3,2) float32
    const float* bias  = (const float*)d_in[2];   // (3,) float32
    float*       out   = (float*)d_out;           // [u0(B) | beliefs(B,2) | log_cf(B,2)]

    init_logp_kernel<<<1, 32>>>(W, bias);
    sample_kernel<<<BATCH / 256, 256>>>(cards, out);
}